// round 14
// baseline (speedup 1.0000x reference)
#include <cuda_runtime.h>

#define Nn 8
#define Cc 64
#define Hh 256
#define Ww 256
#define Pp 8           // cluster: 8 column groups; CTA = all 64 out-ch x 32 cols
#define NT 256         // 8 warps: warp = 8 out-ch x 32 cols
#define HW (Hh*Ww)
#define FSTR 34

// float-index smem offsets
#define WS_F 0                          // weights [64 i][3 tap][64 o] = 12288
#define FBA_F(p) (12288 + (p)*2176)     // chain A fn window [64][34], parity (LOCAL)
#define FBB_F(p) (16640 + (p)*2176)     // chain B
#define MLA_F(p) (20992 + (p)*1024)     // chain A mail [8 rank][sum64|sq64], parity
#define MLB_F(p) (23040 + (p)*1024)
#define YHA_F(p) (25088 + (p)*128)      // chain A y halo [64 ch][L,R], parity
#define YHB_F(p) (25344 + (p)*128)
#define MRA_F 25600                     // mean[64]|rstd[64]
#define MRB_F 25728
#define SM_TOT 25856
#define SMEM_BYTES (SM_TOT*4)           // 103424 B

__device__ float g_stack[(size_t)Nn * Cc * Hh * Ww];

extern __shared__ float sm[];

__device__ __forceinline__ void carr() {
    asm volatile("barrier.cluster.arrive.aligned;" ::: "memory");
}
__device__ __forceinline__ void cwait() {
    asm volatile("barrier.cluster.wait.aligned;" ::: "memory");
}
__device__ __forceinline__ void csync() { carr(); cwait(); }
__device__ __forceinline__ unsigned mapa_rank(unsigned laddr, unsigned rank) {
    unsigned ra;
    asm("mapa.shared::cluster.u32 %0, %1, %2;" : "=r"(ra) : "r"(laddr), "r"(rank));
    return ra;
}
__device__ __forceinline__ void st_cl_f32(unsigned a, float v) {
    asm volatile("st.shared::cluster.f32 [%0], %1;" :: "r"(a), "f"(v) : "memory");
}
__device__ __forceinline__ void st_cl_b64(unsigned a, unsigned long long v) {
    asm volatile("st.shared::cluster.b64 [%0], %1;" :: "r"(a), "l"(v) : "memory");
}

// ---- packed f32x2 helpers ----
__device__ __forceinline__ unsigned long long splat2(float a) {
    unsigned long long r; unsigned u = __float_as_uint(a);
    asm("mov.b64 %0, {%1, %1};" : "=l"(r) : "r"(u));
    return r;
}
__device__ __forceinline__ void fma2(unsigned long long& d, unsigned long long a, unsigned long long b) {
    asm("fma.rn.f32x2 %0, %1, %2, %0;" : "+l"(d) : "l"(a), "l"(b));
}
__device__ __forceinline__ unsigned long long add2(unsigned long long a, unsigned long long b) {
    unsigned long long d;
    asm("add.rn.f32x2 %0, %1, %2;" : "=l"(d) : "l"(a), "l"(b));
    return d;
}
__device__ __forceinline__ unsigned long long mul2(unsigned long long a, unsigned long long b) {
    unsigned long long d;
    asm("mul.rn.f32x2 %0, %1, %2;" : "=l"(d) : "l"(a), "l"(b));
    return d;
}
__device__ __forceinline__ void unpack2(unsigned long long v, float& lo, float& hi) {
    unsigned ul, uh;
    asm("mov.b64 {%0, %1}, %2;" : "=r"(ul), "=r"(uh) : "l"(v));
    lo = __uint_as_float(ul); hi = __uint_as_float(uh);
}
__device__ __forceinline__ float elu1(float v) {
    return v > 0.f ? v : (__expf(v) - 1.f);
}

// conv (64 out-ch on 8 warps) + y-halo push + butterfly reduce + mail push.
// av[8] returns this thread's raw conv outputs (ch = ob+k, col = w0+lane).
__device__ __forceinline__ void conv_push(
    const float* __restrict__ fbR, const float* __restrict__ Ws,
    int lane, int ob, unsigned mlB, unsigned yhB,
    unsigned rank, int hasL, int hasR,
    unsigned pbL, unsigned pbR, const unsigned* __restrict__ pbAll,
    float* __restrict__ av)
{
    unsigned long long acc0 = 0ull, acc1 = 0ull, acc2 = 0ull, acc3 = 0ull;
#pragma unroll 4
    for (int i = 0; i < Cc; i++) {
        float a0 = fbR[i * FSTR + lane];
        float a1 = fbR[i * FSTR + lane + 1];
        float a2 = fbR[i * FSTR + lane + 2];
        unsigned long long s0 = splat2(a0), s1 = splat2(a1), s2 = splat2(a2);
        const ulonglong2* wp = (const ulonglong2*)(Ws + i * 192 + ob);
        ulonglong2 t0a = wp[0],  t0b = wp[1];
        ulonglong2 t1a = wp[16], t1b = wp[17];
        ulonglong2 t2a = wp[32], t2b = wp[33];
        fma2(acc0, s0, t0a.x); fma2(acc1, s0, t0a.y);
        fma2(acc2, s0, t0b.x); fma2(acc3, s0, t0b.y);
        fma2(acc0, s1, t1a.x); fma2(acc1, s1, t1a.y);
        fma2(acc2, s1, t1b.x); fma2(acc3, s1, t1b.y);
        fma2(acc0, s2, t2a.x); fma2(acc1, s2, t2a.y);
        fma2(acc2, s2, t2b.x); fma2(acc3, s2, t2b.y);
    }
    unpack2(acc0, av[0], av[1]);
    unpack2(acc1, av[2], av[3]);
    unpack2(acc2, av[4], av[5]);
    unpack2(acc3, av[6], av[7]);

    // y-halo push: col31 -> right's L slot, col0 -> left's R slot
    if (lane == 31 && hasR) {
#pragma unroll
        for (int k = 0; k < 8; k++)
            st_cl_f32(pbR + yhB + (unsigned)((ob + k) * 2 + 0) * 4u, av[k]);
    }
    if (lane == 0 && hasL) {
#pragma unroll
        for (int k = 0; k < 8; k++)
            st_cl_f32(pbL + yhB + (unsigned)((ob + k) * 2 + 1) * 4u, av[k]);
    }

    // butterfly reduce (packed sum / sumsq) + mail push to all 8 ranks
    unsigned long long s0r = acc0, s1r = acc1, s2r = acc2, s3r = acc3;
    unsigned long long q0r = mul2(acc0, acc0), q1r = mul2(acc1, acc1);
    unsigned long long q2r = mul2(acc2, acc2), q3r = mul2(acc3, acc3);
#pragma unroll
    for (int off = 16; off >= 1; off >>= 1) {
        s0r = add2(s0r, __shfl_xor_sync(0xffffffffu, s0r, off));
        s1r = add2(s1r, __shfl_xor_sync(0xffffffffu, s1r, off));
        s2r = add2(s2r, __shfl_xor_sync(0xffffffffu, s2r, off));
        s3r = add2(s3r, __shfl_xor_sync(0xffffffffu, s3r, off));
        q0r = add2(q0r, __shfl_xor_sync(0xffffffffu, q0r, off));
        q1r = add2(q1r, __shfl_xor_sync(0xffffffffu, q1r, off));
        q2r = add2(q2r, __shfl_xor_sync(0xffffffffu, q2r, off));
        q3r = add2(q3r, __shfl_xor_sync(0xffffffffu, q3r, off));
    }
    if (lane < 8) {
        int j   = lane & 3;
        int isq = lane >> 2;
        unsigned long long val;
        if (isq) val = (j == 0) ? q0r : (j == 1) ? q1r : (j == 2) ? q2r : q3r;
        else     val = (j == 0) ? s0r : (j == 1) ? s1r : (j == 2) ? s2r : s3r;
        unsigned moff = mlB + (unsigned)((int)rank * 128 + isq * 64 + ob + 2 * j) * 4u;
        *(unsigned long long*)((char*)sm + moff) = val;   // local slot
#pragma unroll
        for (int p2 = 0; p2 < 8; p2++)
            if (p2 != (int)rank) st_cl_b64(pbAll[p2] + moff, val);
    }
}

// stats (local mail) + epilogue (own 32 cols from registers + 2 replicated
// halo cols from yh). Includes the MR-visibility syncthreads.
__device__ __forceinline__ void back_half(
    const float* __restrict__ ml, float* __restrict__ mr,
    const float* __restrict__ yh, float* __restrict__ fbW,
    const float* __restrict__ av, const float* __restrict__ xr,
    float xh0, float xh1, float* __restrict__ fn,
    int tid, int lane, int ob, int hasL, int hasR)
{
    if (tid < 64) {
        float sv = 0.f, qv = 0.f;
#pragma unroll
        for (int r2 = 0; r2 < 8; r2++) {
            sv += ml[r2 * 128 + tid];
            qv += ml[r2 * 128 + 64 + tid];
        }
        float mean = sv * (1.f / 256.f);
        float var  = qv * (1.f / 256.f) - mean * mean;
        mr[tid]      = mean;
        mr[64 + tid] = rsqrtf(var + 1e-5f);
    }
    __syncthreads();
#pragma unroll
    for (int k = 0; k < 8; k++) {
        int ch = ob + k;
        float m  = mr[ch];
        float rs = mr[64 + ch];
        float f = elu1((av[k] - m) * rs) + xr[k];
        fn[k] = f;
        fbW[ch * FSTR + 1 + lane] = f;
    }
    if (tid < 64) {
        float m  = mr[tid];
        float rs = mr[64 + tid];
        fbW[tid * FSTR + 0]  = hasL ? (elu1((yh[tid * 2 + 0] - m) * rs) + xh0) : 0.f;
        fbW[tid * FSTR + 33] = hasR ? (elu1((yh[tid * 2 + 1] - m) * rs) + xh1) : 0.f;
    }
}

__global__ void __launch_bounds__(NT, 1) __cluster_dims__(Pp, 1, 1)
dirconv_kernel(const float* __restrict__ x, const float* __restrict__ Wg,
               float* __restrict__ out)
{
    float* Ws = sm;
    const unsigned smu = (unsigned)__cvta_generic_to_shared(sm);

    const int tid  = threadIdx.x;
    const int lane = tid & 31;
    const int warp = tid >> 5;
    const int ob   = warp * 8;
    unsigned rank;
    asm("mov.u32 %0, %%cluster_ctarank;" : "=r"(rank));
    const int g    = (int)rank;
    const int w0   = g * 32;
    const int cid  = blockIdx.x / Pp;     // 0..3: two batches per cluster
    const int hasL = (g > 0), hasR = (g < 7);

    const float* xbA = x + (size_t)(2 * cid) * Cc * HW;
    const float* xbB = x + (size_t)(2 * cid + 1) * Cc * HW;
    float* stkA = g_stack + (size_t)(2 * cid) * Cc * HW;
    float* stkB = g_stack + (size_t)(2 * cid + 1) * Cc * HW;
    float* outA = out + (size_t)(2 * cid) * Cc * HW;
    float* outB = out + (size_t)(2 * cid + 1) * Cc * HW;

    const unsigned pbL = mapa_rank(smu, hasL ? rank - 1u : 0u);
    const unsigned pbR = mapa_rank(smu, hasR ? rank + 1u : 0u);
    unsigned pbAll[8];
#pragma unroll
    for (int p2 = 0; p2 < 8; p2++) pbAll[p2] = mapa_rank(smu, (unsigned)p2);

    // stage weights: Ws[i*192 + tap*64 + o] = W[o][i][1][tap] (bias cancels in IN)
    for (int idx = tid; idx < 12288; idx += NT) {
        int i   = idx / 192;
        int rem = idx - i * 192;
        int tap = rem >> 6;
        int o   = rem & 63;
        Ws[idx] = Wg[(size_t)o * 576 + i * 9 + 3 + tap];
    }

    // f[0] = x[0] windows for both chains (full 34-col, edge-masked);
    // own 32-col blocks -> stack row 0
    for (int idx = tid; idx < 2176; idx += NT) {
        int ch = idx / 34;
        int c  = idx - ch * 34;
        int gcol = w0 - 1 + c;
        int valid = (gcol >= 0 && gcol < Ww);
        sm[FBA_F(0) + idx] = valid ? xbA[(size_t)ch * HW + gcol] : 0.f;
        sm[FBB_F(0) + idx] = valid ? xbB[(size_t)ch * HW + gcol] : 0.f;
    }
    for (int idx = tid; idx < 2048; idx += NT) {
        int ch = idx >> 5, c = idx & 31;
        stkA[(size_t)ch * HW + w0 + c] = xbA[(size_t)ch * HW + w0 + c];
        stkB[(size_t)ch * HW + w0 + c] = xbB[(size_t)ch * HW + w0 + c];
    }

    // residual prefetch for t=1
    float xrA[8], xrB[8], fnA[8], fnB[8], avA[8], avB[8];
#pragma unroll
    for (int k = 0; k < 8; k++) {
        xrA[k] = xbA[(size_t)(ob + k) * HW + (size_t)1 * Ww + w0 + lane];
        xrB[k] = xbB[(size_t)(ob + k) * HW + (size_t)1 * Ww + w0 + lane];
    }
    __syncthreads();
    csync();   // all CTAs staged

    for (int t = 1; t <= 510; ++t) {
        const int p   = t & 1;
        const int fwd = (t <= 255);
        const int row = fwd ? t : 510 - t;
        const float* __restrict__ srcA = fwd ? xbA : stkA;
        const float* __restrict__ srcB = fwd ? xbB : stkB;

        // ===== A front: conv + pushes (parity p)
        conv_push(sm + FBA_F(p ^ 1), Ws, lane, ob,
                  (unsigned)(MLA_F(p) * 4), (unsigned)(YHA_F(p) * 4),
                  rank, hasL, hasR, pbL, pbR, pbAll, avA);
        carr();                      // φ1: releases A's mail + y-halos

        // ===== B front (hides φ1 flight)
        conv_push(sm + FBB_F(p ^ 1), Ws, lane, ob,
                  (unsigned)(MLB_F(p) * 4), (unsigned)(YHB_F(p) * 4),
                  rank, hasL, hasR, pbL, pbR, pbAll, avB);
        cwait();                     // φ1 done: A data delivered (also CTA sync)

        // ===== A back: deferred wb(t-1), halo residuals, stats+epilogue
        if (t >= 2) {
            const int pfwd = (t - 1) <= 255;
            const int prow = pfwd ? (t - 1) : (511 - t);
            float* __restrict__ pd = pfwd ? stkA : outA;
#pragma unroll
            for (int k = 0; k < 8; k++)
                pd[(size_t)(ob + k) * HW + (size_t)prow * Ww + w0 + lane] = fnA[k];
            if (t == 256) {
#pragma unroll
                for (int k = 0; k < 8; k++)
                    outA[(size_t)(ob + k) * HW + (size_t)255 * Ww + w0 + lane] = fnA[k];
            }
        }
        float xh0 = 0.f, xh1 = 0.f;
        if (tid < 64) {
            if (hasL) xh0 = srcA[(size_t)tid * HW + (size_t)row * Ww + (w0 - 1)];
            if (hasR) xh1 = srcA[(size_t)tid * HW + (size_t)row * Ww + (w0 + 32)];
        }
        back_half(sm + MLA_F(p), sm + MRA_F, sm + YHA_F(p), sm + FBA_F(p),
                  avA, xrA, xh0, xh1, fnA, tid, lane, ob, hasL, hasR);
        carr();                      // φ2: releases B's mail + y-halos

        // prefetch xrA(t+1) (own block; hides φ2 flight)
        if (t < 510) {
            const int tn = t + 1, nf = tn <= 255;
            const int nrow = nf ? tn : 510 - tn;
            const float* __restrict__ ns = nf ? xbA : stkA;
#pragma unroll
            for (int k = 0; k < 8; k++)
                xrA[k] = ns[(size_t)(ob + k) * HW + (size_t)nrow * Ww + w0 + lane];
        }
        cwait();                     // φ2 done: B data delivered (+ CTA sync for fbA)

        // ===== B back
        if (t >= 2) {
            const int pfwd = (t - 1) <= 255;
            const int prow = pfwd ? (t - 1) : (511 - t);
            float* __restrict__ pd = pfwd ? stkB : outB;
#pragma unroll
            for (int k = 0; k < 8; k++)
                pd[(size_t)(ob + k) * HW + (size_t)prow * Ww + w0 + lane] = fnB[k];
            if (t == 256) {
#pragma unroll
                for (int k = 0; k < 8; k++)
                    outB[(size_t)(ob + k) * HW + (size_t)255 * Ww + w0 + lane] = fnB[k];
            }
        }
        float yh0 = 0.f, yh1 = 0.f;
        if (tid < 64) {
            if (hasL) yh0 = srcB[(size_t)tid * HW + (size_t)row * Ww + (w0 - 1)];
            if (hasR) yh1 = srcB[(size_t)tid * HW + (size_t)row * Ww + (w0 + 32)];
        }
        back_half(sm + MLB_F(p), sm + MRB_F, sm + YHB_F(p), sm + FBB_F(p),
                  avB, xrB, yh0, yh1, fnB, tid, lane, ob, hasL, hasR);

        // prefetch xrB(t+1) (after wb_B(row) for the t=255 -> row 254 case)
        if (t < 510) {
            const int tn = t + 1, nf = tn <= 255;
            const int nrow = nf ? tn : 510 - tn;
            const float* __restrict__ ns = nf ? xbB : stkB;
#pragma unroll
            for (int k = 0; k < 8; k++)
                xrB[k] = ns[(size_t)(ob + k) * HW + (size_t)nrow * Ww + w0 + lane];
        }
        __syncthreads();             // fbB complete before next iter's conv_B
    }

    // tail: row 0 outputs (t=510 epilogues) for both chains
#pragma unroll
    for (int k = 0; k < 8; k++) {
        outA[(size_t)(ob + k) * HW + w0 + lane] = fnA[k];
        outB[(size_t)(ob + k) * HW + w0 + lane] = fnB[k];
    }

    // no CTA exits while peers may still push into its smem
    csync();
}

extern "C" void kernel_launch(void* const* d_in, const int* in_sizes, int n_in,
                              void* d_out, int out_size)
{
    (void)in_sizes; (void)n_in; (void)out_size;
    const float* x  = (const float*)d_in[0];
    const float* Wg = (const float*)d_in[1];
    // d_in[2] (bias) cancels through InstanceNorm — skipped.
    float* out = (float*)d_out;

    cudaStreamCaptureStatus cs = cudaStreamCaptureStatusNone;
    cudaStreamIsCapturing(0, &cs);
    if (cs == cudaStreamCaptureStatusNone)
        cudaFuncSetAttribute(dirconv_kernel,
                             cudaFuncAttributeMaxDynamicSharedMemorySize, SMEM_BYTES);

    dirconv_kernel<<<(Nn / 2) * Pp, NT, SMEM_BYTES>>>(x, Wg, out);
}

// round 15
// speedup vs baseline: 1.5684x; 1.5684x over previous
#include <cuda_runtime.h>

#define Nn 8
#define Cc 64
#define Hh 256
#define Ww 256
#define Pp 8           // cluster: 8 column groups; CTA = all 64 out-ch x 32 cols
#define NT 256         // 8 warps: warp = 8 out-ch x 32 cols
#define HW (Hh*Ww)
#define FSTR 34

// float-index smem offsets
#define WS_F 0                          // weights [64 i][3 tap][64 o] = 12288
#define FB_F(p) (12288 + (p)*2176)      // fn window [64 ch][34], parity (LOCAL only)
#define ML_F(p) (16640 + (p)*1024)      // mail [8 rank][sum64|sq64], parity
#define YH_F(p) (18688 + (p)*128)       // y halo [64 ch][left,right], parity
#define SM_TOT 18944
#define SMEM_BYTES (SM_TOT*4)           // 75776 B

__device__ float g_stack[(size_t)Nn * Cc * Hh * Ww];

extern __shared__ float sm[];

__device__ __forceinline__ void carr() {
    asm volatile("barrier.cluster.arrive.aligned;" ::: "memory");
}
__device__ __forceinline__ void cwait() {
    asm volatile("barrier.cluster.wait.aligned;" ::: "memory");
}
__device__ __forceinline__ void csync() { carr(); cwait(); }
__device__ __forceinline__ unsigned mapa_rank(unsigned laddr, unsigned rank) {
    unsigned ra;
    asm("mapa.shared::cluster.u32 %0, %1, %2;" : "=r"(ra) : "r"(laddr), "r"(rank));
    return ra;
}
__device__ __forceinline__ void st_cl_f32(unsigned a, float v) {
    asm volatile("st.shared::cluster.f32 [%0], %1;" :: "r"(a), "f"(v) : "memory");
}
__device__ __forceinline__ void st_cl_b64(unsigned a, unsigned long long v) {
    asm volatile("st.shared::cluster.b64 [%0], %1;" :: "r"(a), "l"(v) : "memory");
}

// ---- packed f32x2 helpers ----
__device__ __forceinline__ unsigned long long splat2(float a) {
    unsigned long long r; unsigned u = __float_as_uint(a);
    asm("mov.b64 %0, {%1, %1};" : "=l"(r) : "r"(u));
    return r;
}
__device__ __forceinline__ void fma2(unsigned long long& d, unsigned long long a, unsigned long long b) {
    asm("fma.rn.f32x2 %0, %1, %2, %0;" : "+l"(d) : "l"(a), "l"(b));
}
__device__ __forceinline__ unsigned long long add2(unsigned long long a, unsigned long long b) {
    unsigned long long d;
    asm("add.rn.f32x2 %0, %1, %2;" : "=l"(d) : "l"(a), "l"(b));
    return d;
}
__device__ __forceinline__ unsigned long long mul2(unsigned long long a, unsigned long long b) {
    unsigned long long d;
    asm("mul.rn.f32x2 %0, %1, %2;" : "=l"(d) : "l"(a), "l"(b));
    return d;
}
__device__ __forceinline__ void unpack2(unsigned long long v, float& lo, float& hi) {
    unsigned ul, uh;
    asm("mov.b64 {%0, %1}, %2;" : "=r"(ul), "=r"(uh) : "l"(v));
    lo = __uint_as_float(ul); hi = __uint_as_float(uh);
}
__device__ __forceinline__ float elu1(float v) {
    return v > 0.f ? v : (__expf(v) - 1.f);
}

__global__ void __launch_bounds__(NT, 1) __cluster_dims__(Pp, 1, 1)
dirconv_kernel(const float* __restrict__ x, const float* __restrict__ Wg,
               float* __restrict__ out)
{
    float* Ws = sm;
    const unsigned smu = (unsigned)__cvta_generic_to_shared(sm);

    const int tid  = threadIdx.x;
    const int lane = tid & 31;
    const int warp = tid >> 5;
    const int ob   = warp * 8;            // warp's out-channel base
    unsigned rank;
    asm("mov.u32 %0, %%cluster_ctarank;" : "=r"(rank));
    const int g    = (int)rank;           // column group 0..7
    const int w0   = g * 32;
    const int b    = blockIdx.x / Pp;
    const int hasL = (g > 0), hasR = (g < 7);

    const float* xb = x + (size_t)b * Cc * HW;
    float* stk      = g_stack + (size_t)b * Cc * HW;
    float* outb     = out + (size_t)b * Cc * HW;

    const unsigned pbL = mapa_rank(smu, hasL ? rank - 1u : 0u);
    const unsigned pbR = mapa_rank(smu, hasR ? rank + 1u : 0u);
    unsigned pbAll[8];
#pragma unroll
    for (int p2 = 0; p2 < 8; p2++) pbAll[p2] = mapa_rank(smu, (unsigned)p2);

    // stage weights: Ws[i*192 + tap*64 + o] = W[o][i][1][tap] (bias cancels in IN)
    for (int idx = tid; idx < 12288; idx += NT) {
        int i   = idx / 192;
        int rem = idx - i * 192;
        int tap = rem >> 6;
        int o   = rem & 63;
        Ws[idx] = Wg[(size_t)o * 576 + i * 9 + 3 + tap];
    }

    // f[0] = x[0]: full local window [64 ch][34] (edge-masked); own block -> stack row 0
    for (int idx = tid; idx < 2176; idx += NT) {
        int ch = idx / 34;
        int c  = idx - ch * 34;
        int gcol = w0 - 1 + c;
        sm[FB_F(0) + idx] =
            (gcol >= 0 && gcol < Ww) ? xb[(size_t)ch * HW + gcol] : 0.f;
    }
    for (int idx = tid; idx < 2048; idx += NT) {
        int ch = idx >> 5, c = idx & 31;
        stk[(size_t)ch * HW + w0 + c] = xb[(size_t)ch * HW + w0 + c];
    }
    __syncthreads();
    csync();   // all CTAs staged

    float fn[8];   // this thread's fn(t) for (ch = ob+k, col = w0+lane)

    for (int t = 1; t <= 510; ++t) {
        const int p   = t & 1;
        const int fwd = (t <= 255);
        const int row = fwd ? t : 510 - t;
        const float* __restrict__ src = fwd ? xb : stk;
        const float* fbR = sm + FB_F(p ^ 1);
        float* fbW       = sm + FB_F(p);

        // ===== conv: lane = col, warp owns 8 out-ch as 4 f32x2 pairs
        unsigned long long acc0 = 0ull, acc1 = 0ull, acc2 = 0ull, acc3 = 0ull;
#pragma unroll 4
        for (int i = 0; i < Cc; i++) {
            float a0 = fbR[i * FSTR + lane];
            float a1 = fbR[i * FSTR + lane + 1];
            float a2 = fbR[i * FSTR + lane + 2];
            unsigned long long s0 = splat2(a0), s1 = splat2(a1), s2 = splat2(a2);
            const ulonglong2* wp = (const ulonglong2*)(Ws + i * 192 + ob);
            ulonglong2 t0a = wp[0],  t0b = wp[1];    // tap0: ch pairs
            ulonglong2 t1a = wp[16], t1b = wp[17];   // tap1 (+64 floats)
            ulonglong2 t2a = wp[32], t2b = wp[33];   // tap2 (+128 floats)
            fma2(acc0, s0, t0a.x); fma2(acc1, s0, t0a.y);
            fma2(acc2, s0, t0b.x); fma2(acc3, s0, t0b.y);
            fma2(acc0, s1, t1a.x); fma2(acc1, s1, t1a.y);
            fma2(acc2, s1, t1b.x); fma2(acc3, s1, t1b.y);
            fma2(acc0, s2, t2a.x); fma2(acc1, s2, t2a.y);
            fma2(acc2, s2, t2b.x); fma2(acc3, s2, t2b.y);
        }
        float av[8];
        unpack2(acc0, av[0], av[1]);
        unpack2(acc1, av[2], av[3]);
        unpack2(acc2, av[4], av[5]);
        unpack2(acc3, av[6], av[7]);

        // ===== y-halo push: my col31 -> right's left slot, col0 -> left's right slot
        {
            const unsigned yhB = (unsigned)(YH_F(p) * 4);
            if (lane == 31 && hasR) {
#pragma unroll
                for (int k = 0; k < 8; k++)
                    st_cl_f32(pbR + yhB + (unsigned)((ob + k) * 2 + 0) * 4u, av[k]);
            }
            if (lane == 0 && hasL) {
#pragma unroll
                for (int k = 0; k < 8; k++)
                    st_cl_f32(pbL + yhB + (unsigned)((ob + k) * 2 + 1) * 4u, av[k]);
            }
        }

        // ===== butterfly reduce over 32 cols (packed sum / sumsq) + mail push
        {
            unsigned long long s0r = acc0, s1r = acc1, s2r = acc2, s3r = acc3;
            unsigned long long q0r = mul2(acc0, acc0), q1r = mul2(acc1, acc1);
            unsigned long long q2r = mul2(acc2, acc2), q3r = mul2(acc3, acc3);
#pragma unroll
            for (int off = 16; off >= 1; off >>= 1) {
                s0r = add2(s0r, __shfl_xor_sync(0xffffffffu, s0r, off));
                s1r = add2(s1r, __shfl_xor_sync(0xffffffffu, s1r, off));
                s2r = add2(s2r, __shfl_xor_sync(0xffffffffu, s2r, off));
                s3r = add2(s3r, __shfl_xor_sync(0xffffffffu, s3r, off));
                q0r = add2(q0r, __shfl_xor_sync(0xffffffffu, q0r, off));
                q1r = add2(q1r, __shfl_xor_sync(0xffffffffu, q1r, off));
                q2r = add2(q2r, __shfl_xor_sync(0xffffffffu, q2r, off));
                q3r = add2(q3r, __shfl_xor_sync(0xffffffffu, q3r, off));
            }
            if (lane < 8) {
                int j   = lane & 3;
                int isq = lane >> 2;
                unsigned long long val;
                if (isq) val = (j == 0) ? q0r : (j == 1) ? q1r : (j == 2) ? q2r : q3r;
                else     val = (j == 0) ? s0r : (j == 1) ? s1r : (j == 2) ? s2r : s3r;
                unsigned moff = (unsigned)(ML_F(p) * 4) +
                    (unsigned)((int)rank * 128 + isq * 64 + ob + 2 * j) * 4u;
                *(unsigned long long*)((char*)sm + moff) = val;   // local slot
#pragma unroll
                for (int p2 = 0; p2 < 8; p2++)
                    if (p2 != (int)rank) st_cl_b64(pbAll[p2] + moff, val);
            }
        }

        // ===== arrive as early as possible; hide flight with wb + prefetch
        carr();

        // deferred GMEM writeback of row t-1 (from registers; peers consume it
        // only >= one full barrier later, so post-arrive placement is safe)
        if (t >= 2) {
            const int pfwd = (t - 1) <= 255;
            const int prow = pfwd ? (t - 1) : (511 - t);
            float* __restrict__ pdst = pfwd ? stk : outb;
#pragma unroll
            for (int k = 0; k < 8; k++)
                pdst[(size_t)(ob + k) * HW + (size_t)prow * Ww + w0 + lane] = fn[k];
            if (t == 256) {   // backward init: out[255] = f[255]
#pragma unroll
                for (int k = 0; k < 8; k++)
                    outb[(size_t)(ob + k) * HW + (size_t)255 * Ww + w0 + lane] = fn[k];
            }
        }

        // main residual prefetch (own block; rows written by THIS thread's wb)
        float xr[8];
#pragma unroll
        for (int k = 0; k < 8; k++)
            xr[k] = src[(size_t)(ob + k) * HW + (size_t)row * Ww + w0 + lane];

        cwait();   // mail + y-halos delivered (also orders peers' older wb's)

        // halo residuals (cross-CTA rows -> after the wait) on lanes 0 / 31
        float xhl[8], xhr[8];
        if (lane == 0 && hasL) {
#pragma unroll
            for (int k = 0; k < 8; k++)
                xhl[k] = src[(size_t)(ob + k) * HW + (size_t)row * Ww + (w0 - 1)];
        }
        if (lane == 31 && hasR) {
#pragma unroll
            for (int k = 0; k < 8; k++)
                xhr[k] = src[(size_t)(ob + k) * HW + (size_t)row * Ww + (w0 + 32)];
        }

        // ===== warp-local stats for this warp's 8 channels (no syncthreads)
        // lanes 0-7: sum, lanes 8-15: sumsq for ch = ob + (lane&7)
        float mean_l = 0.f, rstd_l = 0.f;
        {
            const float* ml = sm + ML_F(p);
            int chl = ob + (lane & 7);
            int off = (lane & 8) ? 64 : 0;
            float sv = 0.f;
#pragma unroll
            for (int r2 = 0; r2 < 8; r2++)
                sv += ml[r2 * 128 + off + chl];
            float other = __shfl_xor_sync(0xffffffffu, sv, 8);
            mean_l = sv * (1.f / 256.f);                       // lanes 0-7 valid
            float var = other * (1.f / 256.f) - mean_l * mean_l;
            rstd_l = rsqrtf(fabsf(var) + 1e-5f);               // lanes 0-7 valid
        }

        // ===== epilogue: own 32 cols + 2 halo cols (lanes 0/31), all warp-local
        const float* yh = sm + YH_F(p);
#pragma unroll
        for (int k = 0; k < 8; k++) {
            int ch = ob + k;
            float m  = __shfl_sync(0xffffffffu, mean_l, k);
            float rs = __shfl_sync(0xffffffffu, rstd_l, k);
            float f = elu1((av[k] - m) * rs) + xr[k];
            fn[k] = f;
            fbW[ch * FSTR + 1 + lane] = f;
            if (lane == 0)
                fbW[ch * FSTR + 0] =
                    hasL ? (elu1((yh[ch * 2 + 0] - m) * rs) + xhl[k]) : 0.f;
            if (lane == 31)
                fbW[ch * FSTR + 33] =
                    hasR ? (elu1((yh[ch * 2 + 1] - m) * rs) + xhr[k]) : 0.f;
        }
        __syncthreads();   // fbW complete before next conv
    }

    // final writeback: fn holds row 0 (t=510 epilogue output)
#pragma unroll
    for (int k = 0; k < 8; k++)
        outb[(size_t)(ob + k) * HW + w0 + lane] = fn[k];

    // no CTA exits while peers may still push into its smem
    csync();
}

extern "C" void kernel_launch(void* const* d_in, const int* in_sizes, int n_in,
                              void* d_out, int out_size)
{
    (void)in_sizes; (void)n_in; (void)out_size;
    const float* x  = (const float*)d_in[0];
    const float* Wg = (const float*)d_in[1];
    // d_in[2] (bias) cancels through InstanceNorm — skipped.
    float* out = (float*)d_out;

    cudaStreamCaptureStatus cs = cudaStreamCaptureStatusNone;
    cudaStreamIsCapturing(0, &cs);
    if (cs == cudaStreamCaptureStatusNone)
        cudaFuncSetAttribute(dirconv_kernel,
                             cudaFuncAttributeMaxDynamicSharedMemorySize, SMEM_BYTES);

    dirconv_kernel<<<Nn * Pp, NT, SMEM_BYTES>>>(x, Wg, out);
}

// round 16
// speedup vs baseline: 1.9352x; 1.2338x over previous
#include <cuda_runtime.h>

#define Nn 8
#define Cc 64
#define Hh 256
#define Ww 256
#define Pp 8           // cluster: 8 column groups; CTA = all 64 out-ch x 32 cols
#define NT 256         // 8 warps: warp = 8 out-ch x 32 cols
#define HW (Hh*Ww)
#define FSTR 34

// float-index smem offsets
#define WS_F 0                          // weights [64 i][3 tap][64 o] = 12288
#define FB_F(p) (12288 + (p)*2176)      // fn window [64 ch][34], parity (LOCAL only)
#define ML_F(p) (16640 + (p)*1024)      // mail [8 rank][sum64|sq64], parity
#define YH_F(p) (18688 + (p)*128)       // y halo [64 ch][left,right], parity
#define SM_TOT 18944
#define SMEM_BYTES (SM_TOT*4)           // 75776 B

__device__ float g_stack[(size_t)Nn * Cc * Hh * Ww];

extern __shared__ float sm[];

__device__ __forceinline__ void csync() {
    asm volatile("barrier.cluster.arrive.aligned;" ::: "memory");
    asm volatile("barrier.cluster.wait.aligned;" ::: "memory");
}
__device__ __forceinline__ unsigned mapa_rank(unsigned laddr, unsigned rank) {
    unsigned ra;
    asm("mapa.shared::cluster.u32 %0, %1, %2;" : "=r"(ra) : "r"(laddr), "r"(rank));
    return ra;
}
__device__ __forceinline__ void st_cl_f32(unsigned a, float v) {
    asm volatile("st.shared::cluster.f32 [%0], %1;" :: "r"(a), "f"(v) : "memory");
}
__device__ __forceinline__ void st_cl_b64(unsigned a, unsigned long long v) {
    asm volatile("st.shared::cluster.b64 [%0], %1;" :: "r"(a), "l"(v) : "memory");
}

// ---- packed f32x2 helpers ----
__device__ __forceinline__ unsigned long long splat2(float a) {
    unsigned long long r; unsigned u = __float_as_uint(a);
    asm("mov.b64 %0, {%1, %1};" : "=l"(r) : "r"(u));
    return r;
}
__device__ __forceinline__ void fma2(unsigned long long& d, unsigned long long a, unsigned long long b) {
    asm("fma.rn.f32x2 %0, %1, %2, %0;" : "+l"(d) : "l"(a), "l"(b));
}
__device__ __forceinline__ unsigned long long add2(unsigned long long a, unsigned long long b) {
    unsigned long long d;
    asm("add.rn.f32x2 %0, %1, %2;" : "=l"(d) : "l"(a), "l"(b));
    return d;
}
__device__ __forceinline__ unsigned long long mul2(unsigned long long a, unsigned long long b) {
    unsigned long long d;
    asm("mul.rn.f32x2 %0, %1, %2;" : "=l"(d) : "l"(a), "l"(b));
    return d;
}
__device__ __forceinline__ void unpack2(unsigned long long v, float& lo, float& hi) {
    unsigned ul, uh;
    asm("mov.b64 {%0, %1}, %2;" : "=r"(ul), "=r"(uh) : "l"(v));
    lo = __uint_as_float(ul); hi = __uint_as_float(uh);
}
__device__ __forceinline__ float elu1(float v) {
    return v > 0.f ? v : (__expf(v) - 1.f);
}

__global__ void __launch_bounds__(NT, 1) __cluster_dims__(Pp, 1, 1)
dirconv_kernel(const float* __restrict__ x, const float* __restrict__ Wg,
               float* __restrict__ out)
{
    float* Ws = sm;
    const unsigned smu = (unsigned)__cvta_generic_to_shared(sm);

    const int tid  = threadIdx.x;
    const int lane = tid & 31;
    const int warp = tid >> 5;
    const int ob   = warp * 8;            // warp's out-channel base
    unsigned rank;
    asm("mov.u32 %0, %%cluster_ctarank;" : "=r"(rank));
    const int g    = (int)rank;           // column group 0..7
    const int w0   = g * 32;
    const int b    = blockIdx.x / Pp;
    const int hasL = (g > 0), hasR = (g < 7);

    const float* xb = x + (size_t)b * Cc * HW;
    float* stk      = g_stack + (size_t)b * Cc * HW;
    float* outb     = out + (size_t)b * Cc * HW;

    const unsigned pbL = mapa_rank(smu, hasL ? rank - 1u : 0u);
    const unsigned pbR = mapa_rank(smu, hasR ? rank + 1u : 0u);
    unsigned pbAll[8];
#pragma unroll
    for (int p2 = 0; p2 < 8; p2++) pbAll[p2] = mapa_rank(smu, (unsigned)p2);

    // stage weights: Ws[i*192 + tap*64 + o] = W[o][i][1][tap] (bias cancels in IN)
    for (int idx = tid; idx < 12288; idx += NT) {
        int i   = idx / 192;
        int rem = idx - i * 192;
        int tap = rem >> 6;
        int o   = rem & 63;
        Ws[idx] = Wg[(size_t)o * 576 + i * 9 + 3 + tap];
    }

    // f[0] = x[0]: full local window [64 ch][34] (edge-masked); own block -> stack row 0
    for (int idx = tid; idx < 2176; idx += NT) {
        int ch = idx / 34;
        int c  = idx - ch * 34;
        int gcol = w0 - 1 + c;
        sm[FB_F(0) + idx] =
            (gcol >= 0 && gcol < Ww) ? xb[(size_t)ch * HW + gcol] : 0.f;
    }
    for (int idx = tid; idx < 2048; idx += NT) {
        int ch = idx >> 5, c = idx & 31;
        stk[(size_t)ch * HW + w0 + c] = xb[(size_t)ch * HW + w0 + c];
    }
    __syncthreads();
    csync();   // all CTAs staged

    float fn[8];   // this thread's fn(t) for (ch = ob+k, col = w0+lane)

    for (int t = 1; t <= 510; ++t) {
        const int p   = t & 1;
        const int fwd = (t <= 255);
        const int row = fwd ? t : 510 - t;
        const float* __restrict__ src = fwd ? xb : stk;
        const float* fbR = sm + FB_F(p ^ 1);
        float* fbW       = sm + FB_F(p);

        // ===== conv: lane = col, warp owns 8 out-ch as 4 f32x2 pairs
        unsigned long long acc0 = 0ull, acc1 = 0ull, acc2 = 0ull, acc3 = 0ull;
#pragma unroll 4
        for (int i = 0; i < Cc; i++) {
            float a0 = fbR[i * FSTR + lane];
            float a1 = fbR[i * FSTR + lane + 1];
            float a2 = fbR[i * FSTR + lane + 2];
            unsigned long long s0 = splat2(a0), s1 = splat2(a1), s2 = splat2(a2);
            const ulonglong2* wp = (const ulonglong2*)(Ws + i * 192 + ob);
            ulonglong2 t0a = wp[0],  t0b = wp[1];    // tap0: ch pairs
            ulonglong2 t1a = wp[16], t1b = wp[17];   // tap1 (+64 floats)
            ulonglong2 t2a = wp[32], t2b = wp[33];   // tap2 (+128 floats)
            fma2(acc0, s0, t0a.x); fma2(acc1, s0, t0a.y);
            fma2(acc2, s0, t0b.x); fma2(acc3, s0, t0b.y);
            fma2(acc0, s1, t1a.x); fma2(acc1, s1, t1a.y);
            fma2(acc2, s1, t1b.x); fma2(acc3, s1, t1b.y);
            fma2(acc0, s2, t2a.x); fma2(acc1, s2, t2a.y);
            fma2(acc2, s2, t2b.x); fma2(acc3, s2, t2b.y);
        }
        float av[8];
        unpack2(acc0, av[0], av[1]);
        unpack2(acc1, av[2], av[3]);
        unpack2(acc2, av[4], av[5]);
        unpack2(acc3, av[6], av[7]);

        // ===== y-halo push: my col31 -> right's left slot, col0 -> left's right slot
        {
            const unsigned yhB = (unsigned)(YH_F(p) * 4);
            if (lane == 31 && hasR) {
#pragma unroll
                for (int k = 0; k < 8; k++)
                    st_cl_f32(pbR + yhB + (unsigned)((ob + k) * 2 + 0) * 4u, av[k]);
            }
            if (lane == 0 && hasL) {
#pragma unroll
                for (int k = 0; k < 8; k++)
                    st_cl_f32(pbL + yhB + (unsigned)((ob + k) * 2 + 1) * 4u, av[k]);
            }
        }

        // ===== butterfly reduce over 32 cols (packed sum / sumsq) + mail push
        {
            unsigned long long s0r = acc0, s1r = acc1, s2r = acc2, s3r = acc3;
            unsigned long long q0r = mul2(acc0, acc0), q1r = mul2(acc1, acc1);
            unsigned long long q2r = mul2(acc2, acc2), q3r = mul2(acc3, acc3);
#pragma unroll
            for (int off = 16; off >= 1; off >>= 1) {
                s0r = add2(s0r, __shfl_xor_sync(0xffffffffu, s0r, off));
                s1r = add2(s1r, __shfl_xor_sync(0xffffffffu, s1r, off));
                s2r = add2(s2r, __shfl_xor_sync(0xffffffffu, s2r, off));
                s3r = add2(s3r, __shfl_xor_sync(0xffffffffu, s3r, off));
                q0r = add2(q0r, __shfl_xor_sync(0xffffffffu, q0r, off));
                q1r = add2(q1r, __shfl_xor_sync(0xffffffffu, q1r, off));
                q2r = add2(q2r, __shfl_xor_sync(0xffffffffu, q2r, off));
                q3r = add2(q3r, __shfl_xor_sync(0xffffffffu, q3r, off));
            }
            if (lane < 8) {
                int j   = lane & 3;
                int isq = lane >> 2;
                unsigned long long val;
                if (isq) val = (j == 0) ? q0r : (j == 1) ? q1r : (j == 2) ? q2r : q3r;
                else     val = (j == 0) ? s0r : (j == 1) ? s1r : (j == 2) ? s2r : s3r;
                unsigned moff = (unsigned)(ML_F(p) * 4) +
                    (unsigned)((int)rank * 128 + isq * 64 + ob + 2 * j) * 4u;
                *(unsigned long long*)((char*)sm + moff) = val;   // local slot
#pragma unroll
                for (int p2 = 0; p2 < 8; p2++)
                    if (p2 != (int)rank) st_cl_b64(pbAll[p2] + moff, val);
            }
        }

        // ===== main residual prefetch (own block; self-written stk rows -> safe here)
        float xr[8];
#pragma unroll
        for (int k = 0; k < 8; k++)
            xr[k] = src[(size_t)(ob + k) * HW + (size_t)row * Ww + w0 + lane];

        // ===== the ONE cluster rendezvous per step
        csync();

        // deferred GMEM writeback of row t-1 (from registers; off the fence path)
        if (t >= 2) {
            const int pfwd = (t - 1) <= 255;
            const int prow = pfwd ? (t - 1) : (511 - t);
            float* __restrict__ pdst = pfwd ? stk : outb;
#pragma unroll
            for (int k = 0; k < 8; k++)
                pdst[(size_t)(ob + k) * HW + (size_t)prow * Ww + w0 + lane] = fn[k];
            if (t == 256) {   // backward init: out[255] = f[255]
#pragma unroll
                for (int k = 0; k < 8; k++)
                    outb[(size_t)(ob + k) * HW + (size_t)255 * Ww + w0 + lane] = fn[k];
            }
        }

        // halo residuals for this warp's 8 channels: lanes 0-7 left, 8-15 right
        // (cross-CTA stk rows -> must come AFTER the csync)
        float xh = 0.f;
        {
            int chh = ob + (lane & 7);
            if (lane < 8) {
                if (hasL) xh = src[(size_t)chh * HW + (size_t)row * Ww + (w0 - 1)];
            } else if (lane < 16) {
                if (hasR) xh = src[(size_t)chh * HW + (size_t)row * Ww + (w0 + 32)];
            }
        }

        // ===== warp-local stats for this warp's 8 channels (no syncthreads)
        // lanes 0-7 reduce sums, lanes 8-15 reduce sumsq for ch = ob+(lane&7)
        float mean_l, rstd_l;
        {
            const float* ml = sm + ML_F(p);
            int chl = ob + (lane & 7);
            int off = (lane & 8) ? 64 : 0;
            float sv = 0.f;
#pragma unroll
            for (int r2 = 0; r2 < 8; r2++)
                sv += ml[r2 * 128 + off + chl];
            float other = __shfl_xor_sync(0xffffffffu, sv, 8);
            mean_l = sv * (1.f / 256.f);                        // valid on lanes 0-7
            float var = other * (1.f / 256.f) - mean_l * mean_l;
            rstd_l = rsqrtf(var + 1e-5f);                       // valid on lanes 0-7
        }

        // ===== epilogue: own 32 cols, stats broadcast by shfl (no smem round-trip)
#pragma unroll
        for (int k = 0; k < 8; k++) {
            int ch = ob + k;
            float m  = __shfl_sync(0xffffffffu, mean_l, k);
            float rs = __shfl_sync(0xffffffffu, rstd_l, k);
            float f = elu1((av[k] - m) * rs) + xr[k];
            fn[k] = f;
            fbW[ch * FSTR + 1 + lane] = f;
        }
        // halo columns for this warp's channels: lanes 0-7 left col, 8-15 right col
        {
            float mh = __shfl_sync(0xffffffffu, mean_l, lane & 7);
            float rh = __shfl_sync(0xffffffffu, rstd_l, lane & 7);
            if (lane < 16) {
                int chh = ob + (lane & 7);
                const float* yh = sm + YH_F(p);
                if (lane < 8) {
                    fbW[chh * FSTR + 0] =
                        hasL ? (elu1((yh[chh * 2 + 0] - mh) * rh) + xh) : 0.f;
                } else {
                    fbW[chh * FSTR + 33] =
                        hasR ? (elu1((yh[chh * 2 + 1] - mh) * rh) + xh) : 0.f;
                }
            }
        }
        __syncthreads();   // fbW complete before next conv
    }

    // final writeback: fn holds row 0 (t=510 epilogue output)
#pragma unroll
    for (int k = 0; k < 8; k++)
        outb[(size_t)(ob + k) * HW + w0 + lane] = fn[k];

    // no CTA exits while peers may still push into its smem
    csync();
}

extern "C" void kernel_launch(void* const* d_in, const int* in_sizes, int n_in,
                              void* d_out, int out_size)
{
    (void)in_sizes; (void)n_in; (void)out_size;
    const float* x  = (const float*)d_in[0];
    const float* Wg = (const float*)d_in[1];
    // d_in[2] (bias) cancels through InstanceNorm — skipped.
    float* out = (float*)d_out;

    cudaStreamCaptureStatus cs = cudaStreamCaptureStatusNone;
    cudaStreamIsCapturing(0, &cs);
    if (cs == cudaStreamCaptureStatusNone)
        cudaFuncSetAttribute(dirconv_kernel,
                             cudaFuncAttributeMaxDynamicSharedMemorySize, SMEM_BYTES);

    dirconv_kernel<<<Nn * Pp, NT, SMEM_BYTES>>>(x, Wg, out);
}